// round 4
// baseline (speedup 1.0000x reference)
#include <cuda_runtime.h>
#include <cstdint>

#define BATCH 4
#define SEQ   256
#define CDIM  512
#define HEADS 8
#define HDIM  64
#define BN    1024        // BATCH*SEQ
#define M2    262144      // BATCH*SEQ*SEQ

// -------- scratch (device globals; no allocation allowed) --------
__device__ float g_Q[BN * CDIM];           // Q pre-scaled by 1/sqrt(D)=1/8
__device__ float g_K[BN * CDIM];
__device__ float g_V[BN * CDIM];
__device__ float g_S[(size_t)M2 * HEADS];  // per-head score sums [B,N,N,H]

// -------- helpers --------
__device__ __forceinline__ unsigned f2tf(float x) {
    unsigned u;
    asm("cvt.rna.tf32.f32 %0, %1;" : "=r"(u) : "f"(x));
    return u;
}

__device__ __forceinline__ void mma8(float* c,
                                     unsigned a0, unsigned a1, unsigned a2, unsigned a3,
                                     unsigned b0, unsigned b1) {
    asm volatile(
        "mma.sync.aligned.m16n8k8.row.col.f32.tf32.tf32.f32 "
        "{%0,%1,%2,%3},{%4,%5,%6,%7},{%8,%9},{%0,%1,%2,%3};"
        : "+f"(c[0]), "+f"(c[1]), "+f"(c[2]), "+f"(c[3])
        : "r"(a0), "r"(a1), "r"(a2), "r"(a3), "r"(b0), "r"(b1));
}

__device__ __forceinline__ void cp16(void* s, const void* g) {
    unsigned ss = (unsigned)__cvta_generic_to_shared(s);
    asm volatile("cp.async.cg.shared.global [%0], [%1], 16;" :: "r"(ss), "l"(g));
}
__device__ __forceinline__ void cp_commit() { asm volatile("cp.async.commit_group;"); }
template <int N>
__device__ __forceinline__ void cp_wait() { asm volatile("cp.async.wait_group %0;" :: "n"(N)); }

// =====================================================================
// Pass 1: Q/K/V projections, split-tf32 (3-mma) for ~fp32 accuracy.
// X[1024,512] = h[1024,512] @ W[512,512].  grid=(16,8,3), block=128.
// =====================================================================
__global__ __launch_bounds__(128) void qkv_kernel(
    const float* __restrict__ hmat,
    const float* __restrict__ Wq,
    const float* __restrict__ Wk,
    const float* __restrict__ Wv)
{
    __shared__ float Ah[64][36], Al[64][36];
    __shared__ float Bh[32][72], Bl[32][72];

    int z = blockIdx.z;
    const float* W = (z == 0) ? Wq : ((z == 1) ? Wk : Wv);
    float* Out = (z == 0) ? g_Q : ((z == 1) ? g_K : g_V);
    float scale = (z == 0) ? 0.125f : 1.0f;   // fold 1/sqrt(64) into Q

    int m0 = blockIdx.x * 64, n0 = blockIdx.y * 64;
    int tid = threadIdx.x;
    int w = tid >> 5, lane = tid & 31, g = lane >> 2, q = lane & 3;
    int wr = (w >> 1) * 32, wc = (w & 1) * 32;

    float acc[2][4][4] = {};

    for (int k0 = 0; k0 < 512; k0 += 32) {
        // load + split A (64x32) and B (32x64)
        #pragma unroll
        for (int it = 0; it < 4; it++) {
            int f = tid + it * 128;
            int r = f >> 3, c4 = (f & 7) * 4;
            float4 x = *(const float4*)(hmat + (size_t)(m0 + r) * 512 + k0 + c4);
            float hx = __uint_as_float(f2tf(x.x));
            float hy = __uint_as_float(f2tf(x.y));
            float hz = __uint_as_float(f2tf(x.z));
            float hw = __uint_as_float(f2tf(x.w));
            Ah[r][c4 + 0] = hx; Ah[r][c4 + 1] = hy; Ah[r][c4 + 2] = hz; Ah[r][c4 + 3] = hw;
            Al[r][c4 + 0] = __uint_as_float(f2tf(x.x - hx));
            Al[r][c4 + 1] = __uint_as_float(f2tf(x.y - hy));
            Al[r][c4 + 2] = __uint_as_float(f2tf(x.z - hz));
            Al[r][c4 + 3] = __uint_as_float(f2tf(x.w - hw));
        }
        #pragma unroll
        for (int it = 0; it < 4; it++) {
            int f = tid + it * 128;
            int k = f >> 4, c4 = (f & 15) * 4;
            float4 x = *(const float4*)(W + (size_t)(k0 + k) * 512 + n0 + c4);
            float hx = __uint_as_float(f2tf(x.x));
            float hy = __uint_as_float(f2tf(x.y));
            float hz = __uint_as_float(f2tf(x.z));
            float hw = __uint_as_float(f2tf(x.w));
            Bh[k][c4 + 0] = hx; Bh[k][c4 + 1] = hy; Bh[k][c4 + 2] = hz; Bh[k][c4 + 3] = hw;
            Bl[k][c4 + 0] = __uint_as_float(f2tf(x.x - hx));
            Bl[k][c4 + 1] = __uint_as_float(f2tf(x.y - hy));
            Bl[k][c4 + 2] = __uint_as_float(f2tf(x.z - hz));
            Bl[k][c4 + 3] = __uint_as_float(f2tf(x.w - hw));
        }
        __syncthreads();

        #pragma unroll
        for (int kt = 0; kt < 4; kt++) {
            unsigned ah[2][4], al[2][4];
            #pragma unroll
            for (int m = 0; m < 2; m++) {
                int r = wr + m * 16 + g;
                int kk = kt * 8 + q;
                ah[m][0] = __float_as_uint(Ah[r][kk]);
                ah[m][1] = __float_as_uint(Ah[r + 8][kk]);
                ah[m][2] = __float_as_uint(Ah[r][kk + 4]);
                ah[m][3] = __float_as_uint(Ah[r + 8][kk + 4]);
                al[m][0] = __float_as_uint(Al[r][kk]);
                al[m][1] = __float_as_uint(Al[r + 8][kk]);
                al[m][2] = __float_as_uint(Al[r][kk + 4]);
                al[m][3] = __float_as_uint(Al[r + 8][kk + 4]);
            }
            unsigned bh[4][2], bl[4][2];
            #pragma unroll
            for (int nt = 0; nt < 4; nt++) {
                int cc = wc + nt * 8 + g;
                bh[nt][0] = __float_as_uint(Bh[kt * 8 + q][cc]);
                bh[nt][1] = __float_as_uint(Bh[kt * 8 + q + 4][cc]);
                bl[nt][0] = __float_as_uint(Bl[kt * 8 + q][cc]);
                bl[nt][1] = __float_as_uint(Bl[kt * 8 + q + 4][cc]);
            }
            #pragma unroll
            for (int m = 0; m < 2; m++)
                #pragma unroll
                for (int nt = 0; nt < 4; nt++) {
                    mma8(acc[m][nt], ah[m][0], ah[m][1], ah[m][2], ah[m][3], bh[nt][0], bh[nt][1]);
                    mma8(acc[m][nt], ah[m][0], ah[m][1], ah[m][2], ah[m][3], bl[nt][0], bl[nt][1]);
                    mma8(acc[m][nt], al[m][0], al[m][1], al[m][2], al[m][3], bh[nt][0], bh[nt][1]);
                }
        }
        __syncthreads();
    }

    #pragma unroll
    for (int m = 0; m < 2; m++) {
        int r0 = m0 + wr + m * 16 + g;
        #pragma unroll
        for (int nt = 0; nt < 4; nt++) {
            int c0 = n0 + wc + nt * 8 + 2 * q;
            *(float2*)(Out + (size_t)r0 * 512 + c0) =
                make_float2(acc[m][nt][0] * scale, acc[m][nt][1] * scale);
            *(float2*)(Out + (size_t)(r0 + 8) * 512 + c0) =
                make_float2(acc[m][nt][2] * scale, acc[m][nt][3] * scale);
        }
    }
}

// =====================================================================
// Pass 2: pe = e @ We (tf32), fused epilogue:
//   val = pe * Qs[b,i,n] * K[b,j,n]; e_out <- val (coalesced via smem);
//   g_S[b,i,j,h] <- sum_d val   (each warp owns exactly one head).
// CTA tile 128(m) x 128(n), K chunks of 32, cp.async double buffer.
// grid=(2048,4), block=256.
// =====================================================================
#define AS_STRIDE 36
#define BS_STRIDE 136
#define AS_BUF (128 * AS_STRIDE)
#define BS_BUF (32 * BS_STRIDE)
#define EPI_STRIDE 132
#define PE_SMEM_BYTES ((2 * AS_BUF + 2 * BS_BUF) * 4)

__global__ __launch_bounds__(256, 2) void pe_kernel(
    const float* __restrict__ e,
    const float* __restrict__ We,
    float* __restrict__ out_e)
{
    extern __shared__ float sm[];
    float* As = sm;                 // 2 * 128 * 36
    float* Bs = sm + 2 * AS_BUF;    // 2 * 32 * 136
    float* epi = sm;                // 128 * 132 (aliases GEMM smem after last sync)

    int m0 = blockIdx.x * 128;
    int n0 = blockIdx.y * 128;
    int b = m0 >> 16;
    int i = (m0 >> 8) & 255;
    int j0 = m0 & 255;

    int tid = threadIdx.x;
    int w = tid >> 5, lane = tid & 31, g = lane >> 2, q = lane & 3;
    int wr = (w >> 1) * 32;   // 0,32,64,96
    int wc = (w & 1) * 64;    // 0,64  -> exactly one head per warp

    float acc[2][8][4] = {};

    // prologue: chunk 0
    {
        #pragma unroll
        for (int it = 0; it < 4; it++) {
            int f = tid + it * 256;
            int r = f >> 3, c4 = (f & 7) * 4;
            cp16(As + (size_t)r * AS_STRIDE + c4, e + (size_t)(m0 + r) * 512 + c4);
        }
        #pragma unroll
        for (int it = 0; it < 4; it++) {
            int f = tid + it * 256;
            int k = f >> 5, c4 = (f & 31) * 4;
            cp16(Bs + (size_t)k * BS_STRIDE + c4, We + (size_t)k * 512 + n0 + c4);
        }
        cp_commit();
    }

    for (int kc = 0; kc < 16; kc++) {
        if (kc < 15) {
            int k0 = (kc + 1) * 32;
            float* Ad = As + ((kc + 1) & 1) * AS_BUF;
            float* Bd = Bs + ((kc + 1) & 1) * BS_BUF;
            #pragma unroll
            for (int it = 0; it < 4; it++) {
                int f = tid + it * 256;
                int r = f >> 3, c4 = (f & 7) * 4;
                cp16(Ad + (size_t)r * AS_STRIDE + c4, e + (size_t)(m0 + r) * 512 + k0 + c4);
            }
            #pragma unroll
            for (int it = 0; it < 4; it++) {
                int f = tid + it * 256;
                int k = f >> 5, c4 = (f & 31) * 4;
                cp16(Bd + (size_t)k * BS_STRIDE + c4, We + (size_t)(k0 + k) * 512 + n0 + c4);
            }
            cp_commit();
            cp_wait<1>();
        } else {
            cp_wait<0>();
        }
        __syncthreads();

        const float* Ab = As + (kc & 1) * AS_BUF;
        const float* Bb = Bs + (kc & 1) * BS_BUF;
        #pragma unroll
        for (int kt = 0; kt < 4; kt++) {
            unsigned a[2][4];
            #pragma unroll
            for (int m = 0; m < 2; m++) {
                int r = wr + m * 16 + g;
                int kk = kt * 8 + q;
                a[m][0] = f2tf(Ab[r * AS_STRIDE + kk]);
                a[m][1] = f2tf(Ab[(r + 8) * AS_STRIDE + kk]);
                a[m][2] = f2tf(Ab[r * AS_STRIDE + kk + 4]);
                a[m][3] = f2tf(Ab[(r + 8) * AS_STRIDE + kk + 4]);
            }
            unsigned bb[8][2];
            #pragma unroll
            for (int nt = 0; nt < 8; nt++) {
                int cc = wc + nt * 8 + g;
                bb[nt][0] = f2tf(Bb[(kt * 8 + q) * BS_STRIDE + cc]);
                bb[nt][1] = f2tf(Bb[(kt * 8 + q + 4) * BS_STRIDE + cc]);
            }
            #pragma unroll
            for (int m = 0; m < 2; m++)
                #pragma unroll
                for (int nt = 0; nt < 8; nt++)
                    mma8(acc[m][nt], a[m][0], a[m][1], a[m][2], a[m][3], bb[nt][0], bb[nt][1]);
        }
        __syncthreads();
    }

    // ---------------- epilogue ----------------
    const float* Qrow = g_Q + (size_t)(b * 256 + i) * 512 + n0;            // scaled Q, fixed i
    const float* Kbase = g_K + (size_t)(b * 256 + j0) * 512 + n0;          // row stride 512
    float rsum[4] = {0.f, 0.f, 0.f, 0.f};

    #pragma unroll
    for (int m = 0; m < 2; m++) {
        int lr0 = wr + m * 16 + g;
        int lr1 = lr0 + 8;
        #pragma unroll
        for (int nt = 0; nt < 8; nt++) {
            int col = wc + nt * 8 + 2 * q;
            float2 qv = *(const float2*)(Qrow + col);
            float2 k0v = *(const float2*)(Kbase + (size_t)lr0 * 512 + col);
            float2 k1v = *(const float2*)(Kbase + (size_t)lr1 * 512 + col);
            float v00 = acc[m][nt][0] * qv.x * k0v.x;
            float v01 = acc[m][nt][1] * qv.y * k0v.y;
            float v10 = acc[m][nt][2] * qv.x * k1v.x;
            float v11 = acc[m][nt][3] * qv.y * k1v.y;
            *(float2*)(epi + (size_t)lr0 * EPI_STRIDE + col) = make_float2(v00, v01);
            *(float2*)(epi + (size_t)lr1 * EPI_STRIDE + col) = make_float2(v10, v11);
            rsum[m * 2 + 0] += v00 + v01;
            rsum[m * 2 + 1] += v10 + v11;
        }
    }

    // per-head sums: quad reduce (lanes 4g..4g+3 share rows, cover all 64 cols)
    int hh = (n0 >> 6) + (wc >> 6);
    #pragma unroll
    for (int x = 0; x < 4; x++) {
        float v = rsum[x];
        v += __shfl_xor_sync(0xffffffffu, v, 1);
        v += __shfl_xor_sync(0xffffffffu, v, 2);
        if (q == 0) {
            int lr = wr + (x >> 1) * 16 + g + (x & 1) * 8;
            g_S[((size_t)(b * 256 + i) * 256 + j0 + lr) * 8 + hh] = v;
        }
    }

    __syncthreads();

    // coalesced e_out store from smem stage
    #pragma unroll
    for (int it = 0; it < 16; it++) {
        int f = tid + it * 256;
        int r = f >> 5, c4 = (f & 31) * 4;
        float4 v = *(const float4*)(epi + (size_t)r * EPI_STRIDE + c4);
        *(float4*)(out_e + (size_t)(m0 + r) * 512 + n0 + c4) = v;
    }
}

// =====================================================================
// Pass 3: per (b,i,h): softmax_j(clip(S, -5, 5)), then h_out = w @ V.
// grid = B*N*H = 8192 blocks, 256 threads.
// =====================================================================
__global__ __launch_bounds__(256) void softmax_av_kernel(float* __restrict__ out_h)
{
    __shared__ float ws[256];
    __shared__ float wsum[8];
    __shared__ float pacc[4][64];

    int bid = blockIdx.x;
    int hh = bid & 7;
    int bi = bid >> 3;              // b*256 + i
    int b256 = (bi >> 8) << 8;      // b*256

    int tid = threadIdx.x;
    int wid = tid >> 5, lane = tid & 31;

    float sv = g_S[(size_t)bi * 2048 + (size_t)tid * 8 + hh];
    sv = fminf(5.f, fmaxf(-5.f, sv));
    float ex = expf(sv);
    ws[tid] = ex;

    float v = ex;
    #pragma unroll
    for (int o = 16; o; o >>= 1) v += __shfl_xor_sync(0xffffffffu, v, o);
    if (lane == 0) wsum[wid] = v;
    __syncthreads();

    float tot = 0.f;
    #pragma unroll
    for (int x = 0; x < 8; x++) tot += wsum[x];
    float inv = 1.f / tot;

    int d = tid & 63, part = tid >> 6;
    const float* Vb = g_V + (size_t)b256 * 512 + hh * 64 + d;
    float a = 0.f;
    int jbase = part * 64;
    #pragma unroll 4
    for (int j = 0; j < 64; j++)
        a += ws[jbase + j] * Vb[(size_t)(jbase + j) * 512];
    pacc[part][d] = a;
    __syncthreads();

    if (part == 0) {
        float r = (pacc[0][d] + pacc[1][d] + pacc[2][d] + pacc[3][d]) * inv;
        out_h[(size_t)bi * 512 + hh * 64 + d] = r;
    }
}

// =====================================================================
extern "C" void kernel_launch(void* const* d_in, const int* in_sizes, int n_in,
                              void* d_out, int out_size)
{
    const float* h  = (const float*)d_in[0];
    const float* e  = (const float*)d_in[1];
    const float* Wq = (const float*)d_in[2];
    const float* Wk = (const float*)d_in[3];
    const float* Wv = (const float*)d_in[4];
    const float* We = (const float*)d_in[5];

    float* out = (float*)d_out;
    float* out_h = out;                              // [4,256,512]
    float* out_e = out + (size_t)BN * CDIM;          // [4,256,256,512]

    dim3 g1(16, 8, 3);
    qkv_kernel<<<g1, 128>>>(h, Wq, Wk, Wv);

    cudaFuncSetAttribute(pe_kernel, cudaFuncAttributeMaxDynamicSharedMemorySize, PE_SMEM_BYTES);
    dim3 g2(2048, 4);
    pe_kernel<<<g2, 256, PE_SMEM_BYTES>>>(e, We, out_e);

    softmax_av_kernel<<<8192, 256>>>(out_h);
}

// round 8
// speedup vs baseline: 1.2102x; 1.2102x over previous
#include <cuda_runtime.h>
#include <cstdint>

#define BATCH 4
#define SEQ   256
#define CDIM  512
#define HEADS 8
#define HDIM  64
#define BN    1024        // BATCH*SEQ
#define M2    262144      // BATCH*SEQ*SEQ

// -------- scratch (device globals; no allocation allowed) --------
__device__ float g_Q[BN * CDIM];           // Q pre-scaled by 1/sqrt(D)=1/8
__device__ float g_K[BN * CDIM];
__device__ float g_V[BN * CDIM];
__device__ float g_WeT[CDIM * CDIM];       // We transposed [n][k], RNA tf32-rounded
__device__ float g_S[(size_t)M2 * HEADS];  // per-head score sums [B,N,N,H]

// ==================== PTX helpers (sm_103 baseline ISA only) ====================
__device__ __forceinline__ unsigned f2tf(float x) {
    unsigned u;
    asm("cvt.rna.tf32.f32 %0, %1;" : "=r"(u) : "f"(x));
    return u;
}

__device__ __forceinline__ void mma8(float* c,
                                     unsigned a0, unsigned a1, unsigned a2, unsigned a3,
                                     unsigned b0, unsigned b1) {
    asm volatile(
        "mma.sync.aligned.m16n8k8.row.col.f32.tf32.tf32.f32 "
        "{%0,%1,%2,%3},{%4,%5,%6,%7},{%8,%9},{%0,%1,%2,%3};"
        : "+f"(c[0]), "+f"(c[1]), "+f"(c[2]), "+f"(c[3])
        : "r"(a0), "r"(a1), "r"(a2), "r"(a3), "r"(b0), "r"(b1));
}

__device__ __forceinline__ void ldsm4(unsigned& r0, unsigned& r1, unsigned& r2, unsigned& r3,
                                      uint32_t addr) {
    asm volatile("ldmatrix.sync.aligned.m8n8.x4.shared.b16 {%0,%1,%2,%3}, [%4];"
                 : "=r"(r0), "=r"(r1), "=r"(r2), "=r"(r3) : "r"(addr));
}

__device__ __forceinline__ void cp16(void* s, const void* g) {
    unsigned ss = (unsigned)__cvta_generic_to_shared(s);
    asm volatile("cp.async.cg.shared.global [%0], [%1], 16;" :: "r"(ss), "l"(g));
}
__device__ __forceinline__ void cp_commit() { asm volatile("cp.async.commit_group;"); }
template <int N>
__device__ __forceinline__ void cp_wait() { asm volatile("cp.async.wait_group %0;" :: "n"(N)); }

__device__ __forceinline__ uint32_t smem_u32(const void* p) {
    uint32_t a;
    asm("{ .reg .u64 t; cvta.to.shared.u64 t, %1; cvt.u32.u64 %0, t; }" : "=r"(a) : "l"(p));
    return a;
}

// =====================================================================
// Prep: g_WeT[n][k] = rna_tf32(We[k][n])  (512x512 transpose + round)
// =====================================================================
__global__ __launch_bounds__(256) void prep_weT_kernel(const float* __restrict__ We)
{
    __shared__ float t[32][33];
    int k0 = blockIdx.x * 32, n0 = blockIdx.y * 32;
    int tx = threadIdx.x & 31, ty = threadIdx.x >> 5;
    #pragma unroll
    for (int yy = 0; yy < 4; yy++) {
        int k = ty + yy * 8;
        t[k][tx] = __uint_as_float(f2tf(We[(size_t)(k0 + k) * 512 + n0 + tx]));
    }
    __syncthreads();
    #pragma unroll
    for (int yy = 0; yy < 4; yy++) {
        int n = ty + yy * 8;
        g_WeT[(size_t)(n0 + n) * 512 + k0 + tx] = t[tx][n];
    }
}

// =====================================================================
// Pass 1: Q/K/V projections, split-tf32 (3-mma) for ~fp32 accuracy.
// =====================================================================
__global__ __launch_bounds__(128) void qkv_kernel(
    const float* __restrict__ hmat,
    const float* __restrict__ Wq,
    const float* __restrict__ Wk,
    const float* __restrict__ Wv)
{
    __shared__ float Ah[64][36], Al[64][36];
    __shared__ float Bh[32][72], Bl[32][72];

    int z = blockIdx.z;
    const float* W = (z == 0) ? Wq : ((z == 1) ? Wk : Wv);
    float* Out = (z == 0) ? g_Q : ((z == 1) ? g_K : g_V);
    float scale = (z == 0) ? 0.125f : 1.0f;

    int m0 = blockIdx.x * 64, n0 = blockIdx.y * 64;
    int tid = threadIdx.x;
    int w = tid >> 5, lane = tid & 31, g = lane >> 2, q = lane & 3;
    int wr = (w >> 1) * 32, wc = (w & 1) * 32;

    float acc[2][4][4] = {};

    for (int k0 = 0; k0 < 512; k0 += 32) {
        #pragma unroll
        for (int it = 0; it < 4; it++) {
            int f = tid + it * 128;
            int r = f >> 3, c4 = (f & 7) * 4;
            float4 x = *(const float4*)(hmat + (size_t)(m0 + r) * 512 + k0 + c4);
            float hx = __uint_as_float(f2tf(x.x));
            float hy = __uint_as_float(f2tf(x.y));
            float hz = __uint_as_float(f2tf(x.z));
            float hw = __uint_as_float(f2tf(x.w));
            Ah[r][c4 + 0] = hx; Ah[r][c4 + 1] = hy; Ah[r][c4 + 2] = hz; Ah[r][c4 + 3] = hw;
            Al[r][c4 + 0] = __uint_as_float(f2tf(x.x - hx));
            Al[r][c4 + 1] = __uint_as_float(f2tf(x.y - hy));
            Al[r][c4 + 2] = __uint_as_float(f2tf(x.z - hz));
            Al[r][c4 + 3] = __uint_as_float(f2tf(x.w - hw));
        }
        #pragma unroll
        for (int it = 0; it < 4; it++) {
            int f = tid + it * 128;
            int k = f >> 4, c4 = (f & 15) * 4;
            float4 x = *(const float4*)(W + (size_t)(k0 + k) * 512 + n0 + c4);
            float hx = __uint_as_float(f2tf(x.x));
            float hy = __uint_as_float(f2tf(x.y));
            float hz = __uint_as_float(f2tf(x.z));
            float hw = __uint_as_float(f2tf(x.w));
            Bh[k][c4 + 0] = hx; Bh[k][c4 + 1] = hy; Bh[k][c4 + 2] = hz; Bh[k][c4 + 3] = hw;
            Bl[k][c4 + 0] = __uint_as_float(f2tf(x.x - hx));
            Bl[k][c4 + 1] = __uint_as_float(f2tf(x.y - hy));
            Bl[k][c4 + 2] = __uint_as_float(f2tf(x.z - hz));
            Bl[k][c4 + 3] = __uint_as_float(f2tf(x.w - hw));
        }
        __syncthreads();

        #pragma unroll
        for (int kt = 0; kt < 4; kt++) {
            unsigned ah[2][4], al[2][4];
            #pragma unroll
            for (int m = 0; m < 2; m++) {
                int r = wr + m * 16 + g;
                int kk = kt * 8 + q;
                ah[m][0] = __float_as_uint(Ah[r][kk]);
                ah[m][1] = __float_as_uint(Ah[r + 8][kk]);
                ah[m][2] = __float_as_uint(Ah[r][kk + 4]);
                ah[m][3] = __float_as_uint(Ah[r + 8][kk + 4]);
                al[m][0] = __float_as_uint(Al[r][kk]);
                al[m][1] = __float_as_uint(Al[r + 8][kk]);
                al[m][2] = __float_as_uint(Al[r][kk + 4]);
                al[m][3] = __float_as_uint(Al[r + 8][kk + 4]);
            }
            unsigned bh[4][2], bl[4][2];
            #pragma unroll
            for (int nt = 0; nt < 4; nt++) {
                int cc = wc + nt * 8 + g;
                bh[nt][0] = __float_as_uint(Bh[kt * 8 + q][cc]);
                bh[nt][1] = __float_as_uint(Bh[kt * 8 + q + 4][cc]);
                bl[nt][0] = __float_as_uint(Bl[kt * 8 + q][cc]);
                bl[nt][1] = __float_as_uint(Bl[kt * 8 + q + 4][cc]);
            }
            #pragma unroll
            for (int m = 0; m < 2; m++)
                #pragma unroll
                for (int nt = 0; nt < 4; nt++) {
                    mma8(acc[m][nt], ah[m][0], ah[m][1], ah[m][2], ah[m][3], bh[nt][0], bh[nt][1]);
                    mma8(acc[m][nt], ah[m][0], ah[m][1], ah[m][2], ah[m][3], bl[nt][0], bl[nt][1]);
                    mma8(acc[m][nt], al[m][0], al[m][1], al[m][2], al[m][3], bh[nt][0], bh[nt][1]);
                }
        }
        __syncthreads();
    }

    #pragma unroll
    for (int m = 0; m < 2; m++) {
        int r0 = m0 + wr + m * 16 + g;
        #pragma unroll
        for (int nt = 0; nt < 4; nt++) {
            int c0 = n0 + wc + nt * 8 + 2 * q;
            *(float2*)(Out + (size_t)r0 * 512 + c0) =
                make_float2(acc[m][nt][0] * scale, acc[m][nt][1] * scale);
            *(float2*)(Out + (size_t)(r0 + 8) * 512 + c0) =
                make_float2(acc[m][nt][2] * scale, acc[m][nt][3] * scale);
        }
    }
}

// =====================================================================
// Pass 2 (HMMA + ldmatrix): pe = e @ We (tf32 mma.sync), fused epilogue.
// CTA tile 128(m) x 128(n), K-chunk 32, double-buffered smem:
//   B (g_WeT, pre-rounded tf32) via cp.async; A (e) via reg-staged
//   LDG.128 -> cvt.rna.tf32 -> STS.128 (prefetched across the MMA).
// Fragments via ldmatrix.x4 on padded 144B rows (conflict-free, no cvt).
// Epilogue: acc -> smem stage -> val = pe*q*k -> coalesced e_out store
// + per-head row sums into g_S.   grid=(2048,4), block=256.
// =====================================================================
#define ABUF   18432            // 128 rows * 144 bytes
#define EPI_STRIDE 132
#define PE_SMEM 73728           // 4 * 18432; epi stage (67584 B) aliases

__global__ __launch_bounds__(256, 2) void pe_hmma_kernel(
    const float* __restrict__ e,
    float* __restrict__ out_e)
{
    extern __shared__ char smem[];
    uint32_t sb = smem_u32(smem);

    int tid = threadIdx.x;
    int w = tid >> 5, lane = tid & 31, g = lane >> 2, q = lane & 3;
    int wr = (w >> 1) * 32;   // 0,32,64,96
    int wc = (w & 1) * 64;    // 0,64

    int m0 = blockIdx.x * 128;
    int n0 = blockIdx.y * 128;
    int b = m0 >> 16;
    int i = (m0 >> 8) & 255;
    int j0 = m0 & 255;
    int bi = b * 256 + i;

    int r_cp = tid >> 3, c_cp = tid & 7;   // staging: 16B unit (r_cp+32*it, c_cp)

    // per-lane ldmatrix offsets (byte offsets within a buffer)
    uint32_t a_off = (uint32_t)(((lane & 7) + ((lane >> 3) & 1) * 8) * 144 + (lane >> 4) * 16);
    uint32_t b_off = (uint32_t)(((lane & 7) + (lane >> 4) * 8) * 144 + ((lane >> 3) & 1) * 16);

    const float* eb = e + (size_t)m0 * 512;
    const float* wb = g_WeT + (size_t)n0 * 512;

    float acc[2][8][4] = {};
    float4 av[4];

    auto Bload = [&](int kc, int pp) {
        char* dst = smem + 2 * ABUF + pp * ABUF;
        #pragma unroll
        for (int it = 0; it < 4; it++) {
            int n = r_cp + it * 32;
            cp16(dst + n * 144 + c_cp * 16, wb + (size_t)n * 512 + kc * 32 + c_cp * 4);
        }
        cp_commit();
    };
    auto Aload = [&](int kc) {
        #pragma unroll
        for (int it = 0; it < 4; it++) {
            int r = r_cp + it * 32;
            av[it] = *(const float4*)(eb + (size_t)r * 512 + kc * 32 + c_cp * 4);
        }
    };
    auto Astore = [&](int pp) {
        char* dst = smem + pp * ABUF;
        #pragma unroll
        for (int it = 0; it < 4; it++) {
            int r = r_cp + it * 32;
            float4 v = av[it];
            v.x = __uint_as_float(f2tf(v.x));
            v.y = __uint_as_float(f2tf(v.y));
            v.z = __uint_as_float(f2tf(v.z));
            v.w = __uint_as_float(f2tf(v.w));
            *(float4*)(dst + r * 144 + c_cp * 16) = v;
        }
    };
    auto domma = [&](int pp) {
        uint32_t Ab = sb + pp * ABUF + wr * 144;
        uint32_t Bb = sb + 2 * ABUF + pp * ABUF + wc * 144;
        #pragma unroll
        for (int kt = 0; kt < 4; kt++) {
            unsigned a[2][4];
            #pragma unroll
            for (int m = 0; m < 2; m++)
                ldsm4(a[m][0], a[m][1], a[m][2], a[m][3],
                      Ab + m * (16 * 144) + kt * 32 + a_off);
            unsigned bf[8][2];
            #pragma unroll
            for (int t = 0; t < 4; t++) {
                unsigned r0, r1, r2, r3;
                ldsm4(r0, r1, r2, r3, Bb + t * (16 * 144) + kt * 32 + b_off);
                bf[2 * t][0] = r0; bf[2 * t][1] = r1;
                bf[2 * t + 1][0] = r2; bf[2 * t + 1][1] = r3;
            }
            #pragma unroll
            for (int m = 0; m < 2; m++)
                #pragma unroll
                for (int nt = 0; nt < 8; nt++)
                    mma8(acc[m][nt], a[m][0], a[m][1], a[m][2], a[m][3],
                         bf[nt][0], bf[nt][1]);
        }
    };

    // prologue: chunk 0 into buffer 0
    Bload(0, 0);
    Aload(0);
    Astore(0);
    cp_wait<0>();
    __syncthreads();

    for (int kc = 0; kc < 16; kc++) {
        int p = kc & 1;
        if (kc < 15) {
            Bload(kc + 1, 1 - p);   // cp.async into idle buffer
            Aload(kc + 1);          // global prefetch into regs
        }
        domma(p);
        if (kc < 15) {
            Astore(1 - p);          // cvt + store staged A
            cp_wait<0>();           // B chunk kc+1 arrived
        }
        __syncthreads();
    }

    // ---- epilogue phase A: acc -> smem stage (row-major, stride 132) ----
    float* epi = (float*)smem;
    const float* Qrow = g_Q + (size_t)bi * 512 + n0;
    const float* Kbase = g_K + (size_t)(b * 256 + j0) * 512 + n0;
    float rsum[4] = {0.f, 0.f, 0.f, 0.f};

    #pragma unroll
    for (int m = 0; m < 2; m++) {
        int lr0 = wr + m * 16 + g;
        int lr1 = lr0 + 8;
        #pragma unroll
        for (int nt = 0; nt < 8; nt++) {
            int col = wc + nt * 8 + 2 * q;
            float2 qv = *(const float2*)(Qrow + col);
            float2 k0v = *(const float2*)(Kbase + (size_t)lr0 * 512 + col);
            float2 k1v = *(const float2*)(Kbase + (size_t)lr1 * 512 + col);
            float v00 = acc[m][nt][0] * qv.x * k0v.x;
            float v01 = acc[m][nt][1] * qv.y * k0v.y;
            float v10 = acc[m][nt][2] * qv.x * k1v.x;
            float v11 = acc[m][nt][3] * qv.y * k1v.y;
            *(float2*)(epi + (size_t)lr0 * EPI_STRIDE + col) = make_float2(v00, v01);
            *(float2*)(epi + (size_t)lr1 * EPI_STRIDE + col) = make_float2(v10, v11);
            rsum[m * 2 + 0] += v00 + v01;
            rsum[m * 2 + 1] += v10 + v11;
        }
    }

    // per-head sums: quad reduce (lanes 4g..4g+3 share rows, cover all 64 cols)
    int hh = (n0 >> 6) + (wc >> 6);
    #pragma unroll
    for (int x = 0; x < 4; x++) {
        float v = rsum[x];
        v += __shfl_xor_sync(0xffffffffu, v, 1);
        v += __shfl_xor_sync(0xffffffffu, v, 2);
        if (q == 0) {
            int lr = wr + (x >> 1) * 16 + g + (x & 1) * 8;
            g_S[((size_t)bi * 256 + j0 + lr) * 8 + hh] = v;
        }
    }

    __syncthreads();

    // coalesced e_out store from smem stage
    #pragma unroll
    for (int it = 0; it < 16; it++) {
        int f = tid + it * 256;
        int r = f >> 5, c4 = (f & 31) * 4;
        float4 v = *(const float4*)(epi + (size_t)r * EPI_STRIDE + c4);
        *(float4*)(out_e + (size_t)(m0 + r) * 512 + n0 + c4) = v;
    }
}

// =====================================================================
// Pass 3: per (b,i,h): softmax_j(clip(S, -5, 5)), then h_out = w @ V.
// =====================================================================
__global__ __launch_bounds__(256) void softmax_av_kernel(float* __restrict__ out_h)
{
    __shared__ float ws[256];
    __shared__ float wsum[8];
    __shared__ float pacc[4][64];

    int bid = blockIdx.x;
    int hh = bid & 7;
    int bi = bid >> 3;
    int b256 = (bi >> 8) << 8;

    int tid = threadIdx.x;
    int wid = tid >> 5, lane = tid & 31;

    float sv = g_S[(size_t)bi * 2048 + (size_t)tid * 8 + hh];
    sv = fminf(5.f, fmaxf(-5.f, sv));
    float ex = expf(sv);
    ws[tid] = ex;

    float v = ex;
    #pragma unroll
    for (int o = 16; o; o >>= 1) v += __shfl_xor_sync(0xffffffffu, v, o);
    if (lane == 0) wsum[wid] = v;
    __syncthreads();

    float tot = 0.f;
    #pragma unroll
    for (int x = 0; x < 8; x++) tot += wsum[x];
    float inv = 1.f / tot;

    int d = tid & 63, part = tid >> 6;
    const float* Vb = g_V + (size_t)b256 * 512 + hh * 64 + d;
    float a = 0.f;
    int jbase = part * 64;
    #pragma unroll 4
    for (int j = 0; j < 64; j++)
        a += ws[jbase + j] * Vb[(size_t)(jbase + j) * 512];
    pacc[part][d] = a;
    __syncthreads();

    if (part == 0) {
        float r = (pacc[0][d] + pacc[1][d] + pacc[2][d] + pacc[3][d]) * inv;
        out_h[(size_t)bi * 512 + hh * 64 + d] = r;
    }
}

// =====================================================================
extern "C" void kernel_launch(void* const* d_in, const int* in_sizes, int n_in,
                              void* d_out, int out_size)
{
    const float* h  = (const float*)d_in[0];
    const float* e  = (const float*)d_in[1];
    const float* Wq = (const float*)d_in[2];
    const float* Wk = (const float*)d_in[3];
    const float* Wv = (const float*)d_in[4];
    const float* We = (const float*)d_in[5];

    float* out = (float*)d_out;
    float* out_h = out;                              // [4,256,512]
    float* out_e = out + (size_t)BN * CDIM;          // [4,256,256,512]

    dim3 gp(16, 16);
    prep_weT_kernel<<<gp, 256>>>(We);

    dim3 g1(16, 8, 3);
    qkv_kernel<<<g1, 128>>>(h, Wq, Wk, Wv);

    cudaFuncSetAttribute(pe_hmma_kernel, cudaFuncAttributeMaxDynamicSharedMemorySize, PE_SMEM);
    dim3 g2(2048, 4);
    pe_hmma_kernel<<<g2, 256, PE_SMEM>>>(e, out_e);

    softmax_av_kernel<<<8192, 256>>>(out_h);
}